// round 2
// baseline (speedup 1.0000x reference)
#include <cuda_runtime.h>
#include <math.h>

#define B_ 32
#define T_ 1024
#define J_ 256
#define D_ 512

// ---------------- scratch (static device globals; no allocation) ------------
__device__ float g_S[B_ * T_ * J_];   // 33.5 MB: S, then overwritten by P
__device__ float g_a[B_ * T_];        // ctx . w1
__device__ float g_c[B_ * J_];        // q . w2
__device__ float g_m[B_ * T_];        // rowmax over j
__device__ float g_bt[B_ * T_];       // softmax_t(rowmax)
__device__ float g_h[B_ * D_];        // sum_t bt * ctx

// ---------------- f32x2 helpers ---------------------------------------------
__device__ __forceinline__ unsigned long long pack2(float x) {
    unsigned long long r;
    unsigned u = __float_as_uint(x);
    asm("mov.b64 %0, {%1, %1};" : "=l"(r) : "r"(u));
    return r;
}
__device__ __forceinline__ void fma2(unsigned long long& acc,
                                     unsigned long long a,
                                     unsigned long long b) {
    asm("fma.rn.f32x2 %0, %1, %2, %0;" : "+l"(acc) : "l"(a), "l"(b));
}
__device__ __forceinline__ float2 unpack2(unsigned long long v) {
    unsigned lo, hi;
    asm("mov.b64 {%0, %1}, %2;" : "=r"(lo), "=r"(hi) : "l"(v));
    return make_float2(__uint_as_float(lo), __uint_as_float(hi));
}

// ---------------- kernel 1: a = ctx.w1, c = q.w2 ----------------------------
__global__ __launch_bounds__(256) void dotw_kernel(const float* __restrict__ ctx,
                                                   const float* __restrict__ q,
                                                   const float* __restrict__ w) {
    int gt = blockIdx.x * 256 + threadIdx.x;
    int gw = gt >> 5;
    int lane = gt & 31;
    if (gw >= B_ * T_ + B_ * J_) return;
    const float* rp;
    const float* wp;
    float* op;
    if (gw < B_ * T_) {
        rp = ctx + (size_t)gw * D_;
        wp = w;
        op = g_a + gw;
    } else {
        int r = gw - B_ * T_;
        rp = q + (size_t)r * D_;
        wp = w + D_;
        op = g_c + r;
    }
    const float4* r4 = (const float4*)rp;
    const float4* w4 = (const float4*)wp;
    float s = 0.f;
#pragma unroll
    for (int i = 0; i < 4; i++) {
        float4 x = r4[lane + i * 32];
        float4 ww = w4[lane + i * 32];
        s += x.x * ww.x + x.y * ww.y + x.z * ww.z + x.w * ww.w;
    }
#pragma unroll
    for (int off = 16; off > 0; off >>= 1) s += __shfl_xor_sync(0xffffffffu, s, off);
    if (lane == 0) *op = s;
}

// ---------------- kernel 2: GEMM1  S = (ctx*w3) @ q^T + a + c ---------------
// 128x128x16 tile, 256 threads, 8x8 microtile (f32x2 packed along n).
__global__ __launch_bounds__(256) void gemm1_kernel(const float* __restrict__ ctx,
                                                    const float* __restrict__ q,
                                                    const float* __restrict__ w) {
    __shared__ float As[16][132];
    __shared__ float Bs[16][132];
    __shared__ float w3s[D_];

    const int tid = threadIdx.x;
    const int b = blockIdx.z;
    const int m0 = blockIdx.y * 128;
    const int n0 = blockIdx.x * 128;
    const float* Ag = ctx + (size_t)b * T_ * D_;
    const float* Bg = q + (size_t)b * J_ * D_;

    if (tid < 128) ((float4*)w3s)[tid] = ((const float4*)(w + 2 * D_))[tid];

    const int r0 = tid >> 2;
    const int kc = (tid & 3) * 4;
    const int tx = tid & 15;
    const int ty = tid >> 4;

    const float* aP0 = Ag + (size_t)(m0 + r0) * D_ + kc;
    const float* aP1 = Ag + (size_t)(m0 + 64 + r0) * D_ + kc;
    const float* bP0 = Bg + (size_t)(n0 + r0) * D_ + kc;
    const float* bP1 = Bg + (size_t)(n0 + 64 + r0) * D_ + kc;

    unsigned long long acc[8][4];
#pragma unroll
    for (int i = 0; i < 8; i++)
#pragma unroll
        for (int j = 0; j < 4; j++) acc[i][j] = 0ull;

    float4 aR0 = *(const float4*)aP0;
    float4 aR1 = *(const float4*)aP1;
    float4 bR0 = *(const float4*)bP0;
    float4 bR1 = *(const float4*)bP1;
    __syncthreads();  // w3s ready

    const int KT = D_ / 16;
    for (int kt = 0; kt < KT; kt++) {
        const int k0 = kt * 16;
#pragma unroll
        for (int jj = 0; jj < 4; jj++) {
            float wv = w3s[k0 + kc + jj];
            As[kc + jj][r0]      = (&aR0.x)[jj] * wv;
            As[kc + jj][64 + r0] = (&aR1.x)[jj] * wv;
            Bs[kc + jj][r0]      = (&bR0.x)[jj];
            Bs[kc + jj][64 + r0] = (&bR1.x)[jj];
        }
        __syncthreads();
        if (kt + 1 < KT) {
            aR0 = *(const float4*)(aP0 + (kt + 1) * 16);
            aR1 = *(const float4*)(aP1 + (kt + 1) * 16);
            bR0 = *(const float4*)(bP0 + (kt + 1) * 16);
            bR1 = *(const float4*)(bP1 + (kt + 1) * 16);
        }
#pragma unroll
        for (int kk = 0; kk < 16; kk++) {
            float4 a0 = *(const float4*)&As[kk][ty * 8];
            float4 a1 = *(const float4*)&As[kk][ty * 8 + 4];
            ulonglong2 b0 = *(const ulonglong2*)&Bs[kk][tx * 4];
            ulonglong2 b1 = *(const ulonglong2*)&Bs[kk][tx * 4 + 64];
            const float av[8] = {a0.x, a0.y, a0.z, a0.w, a1.x, a1.y, a1.z, a1.w};
#pragma unroll
            for (int i = 0; i < 8; i++) {
                unsigned long long ar = pack2(av[i]);
                fma2(acc[i][0], ar, b0.x);
                fma2(acc[i][1], ar, b0.y);
                fma2(acc[i][2], ar, b1.x);
                fma2(acc[i][3], ar, b1.y);
            }
        }
        __syncthreads();
    }

    // epilogue: + a[b,m] + c[b,n], write S
    float amv[8];
#pragma unroll
    for (int i = 0; i < 8; i++) amv[i] = g_a[b * T_ + m0 + ty * 8 + i];
    float cn0[4], cn1[4];
#pragma unroll
    for (int j = 0; j < 4; j++) {
        cn0[j] = g_c[b * J_ + n0 + tx * 4 + j];
        cn1[j] = g_c[b * J_ + n0 + tx * 4 + 64 + j];
    }
#pragma unroll
    for (int i = 0; i < 8; i++) {
        float* row = g_S + ((size_t)(b * T_ + m0 + ty * 8 + i)) * J_ + n0;
        float2 u0 = unpack2(acc[i][0]);
        float2 u1 = unpack2(acc[i][1]);
        float2 u2 = unpack2(acc[i][2]);
        float2 u3 = unpack2(acc[i][3]);
        float4 v0 = make_float4(u0.x + amv[i] + cn0[0], u0.y + amv[i] + cn0[1],
                                u1.x + amv[i] + cn0[2], u1.y + amv[i] + cn0[3]);
        float4 v1 = make_float4(u2.x + amv[i] + cn1[0], u2.y + amv[i] + cn1[1],
                                u3.x + amv[i] + cn1[2], u3.y + amv[i] + cn1[3]);
        *(float4*)(row + tx * 4) = v0;
        *(float4*)(row + tx * 4 + 64) = v1;
    }
}

// ---------------- kernel 3: rowmax over j -----------------------------------
__global__ __launch_bounds__(256) void rowmax_kernel() {
    int gw = (blockIdx.x * 256 + threadIdx.x) >> 5;
    int lane = threadIdx.x & 31;
    const float4* p = (const float4*)(g_S + (size_t)gw * J_);
    float4 v1 = p[lane];
    float4 v2 = p[lane + 32];
    float mx = fmaxf(fmaxf(fmaxf(v1.x, v1.y), fmaxf(v1.z, v1.w)),
                     fmaxf(fmaxf(v2.x, v2.y), fmaxf(v2.z, v2.w)));
#pragma unroll
    for (int off = 16; off > 0; off >>= 1) mx = fmaxf(mx, __shfl_xor_sync(0xffffffffu, mx, off));
    if (lane == 0) g_m[gw] = mx;
}

// ---------------- kernel 4: b_t = softmax_t(rowmax) -------------------------
__global__ __launch_bounds__(256) void bt_kernel() {
    const int b = blockIdx.x;
    const int tid = threadIdx.x;
    const int lane = tid & 31;
    const int wid = tid >> 5;
    __shared__ float redA[8], redB[8];

    float4 v = ((const float4*)(g_m + b * T_))[tid];
    float mx = fmaxf(fmaxf(v.x, v.y), fmaxf(v.z, v.w));
#pragma unroll
    for (int off = 16; off > 0; off >>= 1) mx = fmaxf(mx, __shfl_xor_sync(0xffffffffu, mx, off));
    if (lane == 0) redA[wid] = mx;
    __syncthreads();
    float bm = redA[0];
#pragma unroll
    for (int w = 1; w < 8; w++) bm = fmaxf(bm, redA[w]);

    float e0 = expf(v.x - bm), e1 = expf(v.y - bm), e2 = expf(v.z - bm), e3 = expf(v.w - bm);
    float s = e0 + e1 + e2 + e3;
#pragma unroll
    for (int off = 16; off > 0; off >>= 1) s += __shfl_xor_sync(0xffffffffu, s, off);
    if (lane == 0) redB[wid] = s;
    __syncthreads();
    float tot = 0.f;
#pragma unroll
    for (int w = 0; w < 8; w++) tot += redB[w];
    float inv = 1.f / tot;
    ((float4*)(g_bt + b * T_))[tid] = make_float4(e0 * inv, e1 * inv, e2 * inv, e3 * inv);
}

// ---------------- kernel 5: column softmax over t (in place -> P) -----------
__global__ __launch_bounds__(256) void colsoftmax_kernel() {
    const int b = blockIdx.y;
    const int lane = threadIdx.x & 31;
    const int j = blockIdx.x * 32 + lane;
    const int ts = threadIdx.x >> 5;  // 0..7
    float* S = g_S + (size_t)b * T_ * J_;

    float mx = -3.0e38f, sm = 0.f;
    for (int t = ts; t < T_; t += 8) {
        float v = S[t * J_ + j];
        float nm = fmaxf(mx, v);
        sm = sm * expf(mx - nm) + expf(v - nm);
        mx = nm;
    }
    __shared__ float sM[8][32], sS[8][32];
    sM[ts][lane] = mx;
    sS[ts][lane] = sm;
    __syncthreads();
    if (threadIdx.x < 32) {
        float M = sM[0][lane], SS = sS[0][lane];
#pragma unroll
        for (int r = 1; r < 8; r++) {
            float m2 = sM[r][lane], s2 = sS[r][lane];
            float nm = fmaxf(M, m2);
            SS = SS * expf(M - nm) + s2 * expf(m2 - nm);
            M = nm;
        }
        sM[0][lane] = M;
        sS[0][lane] = SS;
    }
    __syncthreads();
    float M = sM[0][lane];
    float inv = 1.f / sS[0][lane];
    for (int t = ts; t < T_; t += 8) {
        float v = S[t * J_ + j];
        S[t * J_ + j] = expf(v - M) * inv;
    }
}

// ---------------- kernel 6: h[b,d] = sum_t bt * ctx -------------------------
__global__ __launch_bounds__(256) void h_kernel(const float* __restrict__ ctx) {
    const int b = blockIdx.y;
    const int d = blockIdx.x * 256 + threadIdx.x;
    __shared__ float bts[T_];
    for (int i = threadIdx.x; i < T_; i += 256) bts[i] = g_bt[b * T_ + i];
    __syncthreads();
    const float* cp = ctx + (size_t)b * T_ * D_ + d;
    float acc = 0.f;
#pragma unroll 4
    for (int t = 0; t < T_; t++) acc += bts[t] * cp[(size_t)t * D_];
    g_h[b * D_ + d] = acc;
}

// ---------------- kernel 7: GEMM2  U = P @ q, fused G assembly --------------
__global__ __launch_bounds__(256) void gemm2_kernel(const float* __restrict__ ctx,
                                                    const float* __restrict__ q,
                                                    float* __restrict__ out) {
    __shared__ float As[16][132];
    __shared__ float Bs[16][132];

    const int tid = threadIdx.x;
    const int b = blockIdx.z;
    const int m0 = blockIdx.y * 128;
    const int n0 = blockIdx.x * 128;
    const float* Ag = g_S + (size_t)b * T_ * J_;   // P, [1024][256]
    const float* Bg = q + (size_t)b * J_ * D_;     // [256][512], n contiguous

    const int r0 = tid >> 2;
    const int kc = (tid & 3) * 4;
    const int kb = tid >> 5;        // B-load: k row 0..7
    const int nc = tid & 31;        // B-load: float4 col
    const int tx = tid & 15;
    const int ty = tid >> 4;

    const float* aP0 = Ag + (size_t)(m0 + r0) * J_ + kc;
    const float* aP1 = Ag + (size_t)(m0 + 64 + r0) * J_ + kc;
    const float* bP0 = Bg + (size_t)kb * D_ + n0 + nc * 4;
    const float* bP1 = Bg + (size_t)(kb + 8) * D_ + n0 + nc * 4;

    unsigned long long acc[8][4];
#pragma unroll
    for (int i = 0; i < 8; i++)
#pragma unroll
        for (int j = 0; j < 4; j++) acc[i][j] = 0ull;

    float4 aR0 = *(const float4*)aP0;
    float4 aR1 = *(const float4*)aP1;
    float4 bR0 = *(const float4*)bP0;
    float4 bR1 = *(const float4*)bP1;

    const int KT = J_ / 16;
    for (int kt = 0; kt < KT; kt++) {
#pragma unroll
        for (int jj = 0; jj < 4; jj++) {
            As[kc + jj][r0]      = (&aR0.x)[jj];
            As[kc + jj][64 + r0] = (&aR1.x)[jj];
        }
        *(float4*)&Bs[kb][nc * 4] = bR0;
        *(float4*)&Bs[kb + 8][nc * 4] = bR1;
        __syncthreads();
        if (kt + 1 < KT) {
            aR0 = *(const float4*)(aP0 + (kt + 1) * 16);
            aR1 = *(const float4*)(aP1 + (kt + 1) * 16);
            bR0 = *(const float4*)(bP0 + (size_t)(kt + 1) * 16 * D_);
            bR1 = *(const float4*)(bP1 + (size_t)(kt + 1) * 16 * D_);
        }
#pragma unroll
        for (int kk = 0; kk < 16; kk++) {
            float4 a0 = *(const float4*)&As[kk][ty * 8];
            float4 a1 = *(const float4*)&As[kk][ty * 8 + 4];
            ulonglong2 b0 = *(const ulonglong2*)&Bs[kk][tx * 4];
            ulonglong2 b1 = *(const ulonglong2*)&Bs[kk][tx * 4 + 64];
            const float av[8] = {a0.x, a0.y, a0.z, a0.w, a1.x, a1.y, a1.z, a1.w};
#pragma unroll
            for (int i = 0; i < 8; i++) {
                unsigned long long ar = pack2(av[i]);
                fma2(acc[i][0], ar, b0.x);
                fma2(acc[i][1], ar, b0.y);
                fma2(acc[i][2], ar, b1.x);
                fma2(acc[i][3], ar, b1.y);
            }
        }
        __syncthreads();
    }

    // epilogue: G = [ctx | U | ctx*U | ctx*h]
    const int c0off = n0 + tx * 4;
    float4 h0 = *(const float4*)(g_h + b * D_ + c0off);
    float4 h1 = *(const float4*)(g_h + b * D_ + c0off + 64);
#pragma unroll
    for (int i = 0; i < 8; i++) {
        const int m = m0 + ty * 8 + i;
        const float* crow = ctx + ((size_t)(b * T_ + m)) * D_;
        float* orow = out + ((size_t)(b * T_ + m)) * (4 * D_);
        float4 cA = *(const float4*)(crow + c0off);
        float4 cB = *(const float4*)(crow + c0off + 64);
        float2 u0 = unpack2(acc[i][0]);
        float2 u1 = unpack2(acc[i][1]);
        float2 u2 = unpack2(acc[i][2]);
        float2 u3 = unpack2(acc[i][3]);
        float4 uA = make_float4(u0.x, u0.y, u1.x, u1.y);
        float4 uB = make_float4(u2.x, u2.y, u3.x, u3.y);

        *(float4*)(orow + c0off) = cA;
        *(float4*)(orow + c0off + 64) = cB;
        *(float4*)(orow + D_ + c0off) = uA;
        *(float4*)(orow + D_ + c0off + 64) = uB;
        *(float4*)(orow + 2 * D_ + c0off) =
            make_float4(cA.x * uA.x, cA.y * uA.y, cA.z * uA.z, cA.w * uA.w);
        *(float4*)(orow + 2 * D_ + c0off + 64) =
            make_float4(cB.x * uB.x, cB.y * uB.y, cB.z * uB.z, cB.w * uB.w);
        *(float4*)(orow + 3 * D_ + c0off) =
            make_float4(cA.x * h0.x, cA.y * h0.y, cA.z * h0.z, cA.w * h0.w);
        *(float4*)(orow + 3 * D_ + c0off + 64) =
            make_float4(cB.x * h1.x, cB.y * h1.y, cB.z * h1.z, cB.w * h1.w);
    }
}

// ---------------- launch -----------------------------------------------------
extern "C" void kernel_launch(void* const* d_in, const int* in_sizes, int n_in,
                              void* d_out, int out_size) {
    const float* ctx = (const float*)d_in[0];
    const float* q = (const float*)d_in[1];
    const float* w = (const float*)d_in[2];
    float* out = (float*)d_out;

    dotw_kernel<<<5120, 256>>>(ctx, q, w);
    gemm1_kernel<<<dim3(2, 8, 32), 256>>>(ctx, q, w);
    rowmax_kernel<<<4096, 256>>>();
    bt_kernel<<<32, 256>>>();
    colsoftmax_kernel<<<dim3(8, 32), 256>>>();
    h_kernel<<<dim3(2, 32), 256>>>(ctx);
    gemm2_kernel<<<dim3(4, 8, 32), 256>>>(ctx, q, out);
}

// round 5
// speedup vs baseline: 1.0545x; 1.0545x over previous
#include <cuda_runtime.h>
#include <math.h>

#define B_ 32
#define T_ 1024
#define J_ 256
#define D_ 512

// ---------------- scratch (static device globals; no allocation) ------------
__device__ float g_S[B_ * T_ * J_];   // 33.5 MB: S, then overwritten by P
__device__ float g_a[B_ * T_];        // ctx . w1
__device__ float g_c[B_ * J_];        // q . w2
__device__ float g_m[B_ * T_];        // rowmax over j
__device__ float g_bt[B_ * T_];       // softmax_t(rowmax)
__device__ float g_h[B_ * D_];        // sum_t bt * ctx

// ---------------- tf32 helpers ----------------------------------------------
__device__ __forceinline__ float tf32r(float x) {
    unsigned u;
    asm("cvt.rna.tf32.f32 %0, %1;" : "=r"(u) : "f"(x));
    return __uint_as_float(u);
}

#define MMA_TF32(c, af, b2)                                                     \
    asm("mma.sync.aligned.m16n8k8.row.col.f32.tf32.tf32.f32 "                   \
        "{%0,%1,%2,%3},{%4,%5,%6,%7},{%8,%9},{%0,%1,%2,%3};"                    \
        : "+f"((c)[0]), "+f"((c)[1]), "+f"((c)[2]), "+f"((c)[3])                \
        : "r"(__float_as_uint((af).x)), "r"(__float_as_uint((af).y)),           \
          "r"(__float_as_uint((af).z)), "r"(__float_as_uint((af).w)),           \
          "r"(__float_as_uint((b2).x)), "r"(__float_as_uint((b2).y)))

// ---------------- kernel 1: a = ctx.w1, c = q.w2 ----------------------------
__global__ __launch_bounds__(256) void dotw_kernel(const float* __restrict__ ctx,
                                                   const float* __restrict__ q,
                                                   const float* __restrict__ w) {
    int gt = blockIdx.x * 256 + threadIdx.x;
    int gw = gt >> 5;
    int lane = gt & 31;
    if (gw >= B_ * T_ + B_ * J_) return;
    const float* rp;
    const float* wp;
    float* op;
    if (gw < B_ * T_) {
        rp = ctx + (size_t)gw * D_;
        wp = w;
        op = g_a + gw;
    } else {
        int r = gw - B_ * T_;
        rp = q + (size_t)r * D_;
        wp = w + D_;
        op = g_c + r;
    }
    const float4* r4 = (const float4*)rp;
    const float4* w4 = (const float4*)wp;
    float s = 0.f;
#pragma unroll
    for (int i = 0; i < 4; i++) {
        float4 x = r4[lane + i * 32];
        float4 ww = w4[lane + i * 32];
        s += x.x * ww.x + x.y * ww.y + x.z * ww.z + x.w * ww.w;
    }
#pragma unroll
    for (int off = 16; off > 0; off >>= 1) s += __shfl_xor_sync(0xffffffffu, s, off);
    if (lane == 0) *op = s;
}

// ---------------- kernel 2: GEMM1  S = (ctx*w3) @ q^T + a + c  (tf32 mma) ---
// Block 128x128, K-tile 32, 256 threads = 8 warps in 2(m) x 4(n), warp tile
// 64x32. SMEM holds pre-permuted tf32 fragments: A read = 1x lds.128/frag,
// B read = 1x lds.64/frag, both conflict-free.
__global__ __launch_bounds__(256) void gemm1_tc(const float* __restrict__ ctx,
                                                const float* __restrict__ q,
                                                const float* __restrict__ w) {
    __shared__ float As[4 * 8 * 128];   // [ka][matom][lane*4 + r]
    __shared__ float Bs[4 * 16 * 64];   // [ka][natom][lane*2 + r]
    __shared__ float w3s[D_];

    const int tid = threadIdx.x;
    const int b = blockIdx.z;
    const int m0 = blockIdx.y * 128;
    const int n0 = blockIdx.x * 128;
    const float* Ag = ctx + (size_t)b * T_ * D_;
    const float* Bg = q + (size_t)b * J_ * D_;

    if (tid < 128) ((float4*)w3s)[tid] = ((const float4*)(w + 2 * D_))[tid];

    const int lane = tid & 31;
    const int wid = tid >> 5;
    const int warp_m = wid & 1;
    const int warp_n = wid >> 1;

    float acc[4][4][4];
#pragma unroll
    for (int i = 0; i < 4; i++)
#pragma unroll
        for (int j = 0; j < 4; j++)
#pragma unroll
            for (int k = 0; k < 4; k++) acc[i][j][k] = 0.f;

    float4 pa[4], pb[4];
#pragma unroll
    for (int i = 0; i < 4; i++) {
        int f = tid + i * 256;
        int m = f >> 3, k4 = f & 7;
        pa[i] = *(const float4*)(Ag + (size_t)(m0 + m) * D_ + k4 * 4);
        pb[i] = *(const float4*)(Bg + (size_t)(n0 + m) * D_ + k4 * 4);
    }
    __syncthreads();  // w3s ready

    const int KT = D_ / 32;
    for (int kt = 0; kt < KT; kt++) {
#pragma unroll
        for (int i = 0; i < 4; i++) {
            int f = tid + i * 256;
            int m = f >> 3, k4 = f & 7;
            int ka = k4 >> 1;
            // A scatter (with w3 scaling)
            {
                int matom = m >> 4, mr = m & 15;
                int ls = (mr & 7) * 4;
                int r = (mr >> 3) + 2 * (k4 & 1);
                float* dst = As + ((ka * 8 + matom) << 7) + r;
#pragma unroll
                for (int j = 0; j < 4; j++)
                    dst[(ls + j) * 4] = tf32r((&pa[i].x)[j] * w3s[kt * 32 + k4 * 4 + j]);
            }
            // B scatter
            {
                int natom = m >> 3, nr = m & 7;
                int ls = nr * 4;
                int r = k4 & 1;
                float* dst = Bs + ((ka * 16 + natom) << 6) + r;
#pragma unroll
                for (int j = 0; j < 4; j++) dst[(ls + j) * 2] = tf32r((&pb[i].x)[j]);
            }
        }
        __syncthreads();
        if (kt + 1 < KT) {
#pragma unroll
            for (int i = 0; i < 4; i++) {
                int f = tid + i * 256;
                int m = f >> 3, k4 = f & 7;
                pa[i] = *(const float4*)(Ag + (size_t)(m0 + m) * D_ + (kt + 1) * 32 + k4 * 4);
                pb[i] = *(const float4*)(Bg + (size_t)(n0 + m) * D_ + (kt + 1) * 32 + k4 * 4);
            }
        }
#pragma unroll
        for (int ka = 0; ka < 4; ka++) {
            float4 af[4];
            float2 bf[4];
#pragma unroll
            for (int ma = 0; ma < 4; ma++)
                af[ma] = *(const float4*)&As[((ka * 8 + warp_m * 4 + ma) << 7) + lane * 4];
#pragma unroll
            for (int na = 0; na < 4; na++)
                bf[na] = *(const float2*)&Bs[((ka * 16 + warp_n * 4 + na) << 6) + lane * 2];
#pragma unroll
            for (int ma = 0; ma < 4; ma++)
#pragma unroll
                for (int na = 0; na < 4; na++) MMA_TF32(acc[ma][na], af[ma], bf[na]);
        }
        __syncthreads();
    }

    // epilogue: + a[b,m] + c[b,n]
    const int g = lane >> 2;
    const int tg = lane & 3;
#pragma unroll
    for (int ma = 0; ma < 4; ma++) {
        int r0 = m0 + warp_m * 64 + ma * 16 + g;
        float a0v = g_a[b * T_ + r0];
        float a1v = g_a[b * T_ + r0 + 8];
#pragma unroll
        for (int na = 0; na < 4; na++) {
            int n = n0 + warp_n * 32 + na * 8 + tg * 2;
            float c0 = g_c[b * J_ + n];
            float c1 = g_c[b * J_ + n + 1];
            float* p0 = g_S + (size_t)(b * T_ + r0) * J_ + n;
            *(float2*)p0 = make_float2(acc[ma][na][0] + a0v + c0, acc[ma][na][1] + a0v + c1);
            *(float2*)(p0 + 8 * J_) =
                make_float2(acc[ma][na][2] + a1v + c0, acc[ma][na][3] + a1v + c1);
        }
    }
}

// ---------------- kernel 3: rowmax over j -----------------------------------
__global__ __launch_bounds__(256) void rowmax_kernel() {
    int gw = (blockIdx.x * 256 + threadIdx.x) >> 5;
    int lane = threadIdx.x & 31;
    const float4* p = (const float4*)(g_S + (size_t)gw * J_);
    float4 v1 = p[lane];
    float4 v2 = p[lane + 32];
    float mx = fmaxf(fmaxf(fmaxf(v1.x, v1.y), fmaxf(v1.z, v1.w)),
                     fmaxf(fmaxf(v2.x, v2.y), fmaxf(v2.z, v2.w)));
#pragma unroll
    for (int off = 16; off > 0; off >>= 1) mx = fmaxf(mx, __shfl_xor_sync(0xffffffffu, mx, off));
    if (lane == 0) g_m[gw] = mx;
}

// ---------------- kernel 4: b_t = softmax_t(rowmax) -------------------------
__global__ __launch_bounds__(256) void bt_kernel() {
    const int b = blockIdx.x;
    const int tid = threadIdx.x;
    const int lane = tid & 31;
    const int wid = tid >> 5;
    __shared__ float redA[8], redB[8];

    float4 v = ((const float4*)(g_m + b * T_))[tid];
    float mx = fmaxf(fmaxf(v.x, v.y), fmaxf(v.z, v.w));
#pragma unroll
    for (int off = 16; off > 0; off >>= 1) mx = fmaxf(mx, __shfl_xor_sync(0xffffffffu, mx, off));
    if (lane == 0) redA[wid] = mx;
    __syncthreads();
    float bm = redA[0];
#pragma unroll
    for (int w = 1; w < 8; w++) bm = fmaxf(bm, redA[w]);

    float e0 = expf(v.x - bm), e1 = expf(v.y - bm), e2 = expf(v.z - bm), e3 = expf(v.w - bm);
    float s = e0 + e1 + e2 + e3;
#pragma unroll
    for (int off = 16; off > 0; off >>= 1) s += __shfl_xor_sync(0xffffffffu, s, off);
    if (lane == 0) redB[wid] = s;
    __syncthreads();
    float tot = 0.f;
#pragma unroll
    for (int w = 0; w < 8; w++) tot += redB[w];
    float inv = 1.f / tot;
    ((float4*)(g_bt + b * T_))[tid] = make_float4(e0 * inv, e1 * inv, e2 * inv, e3 * inv);
}

// ---------------- kernel 5: column softmax over t (in place -> P) -----------
__global__ __launch_bounds__(256) void colsoftmax_kernel() {
    const int b = blockIdx.y;
    const int lane = threadIdx.x & 31;
    const int j = blockIdx.x * 32 + lane;
    const int ts = threadIdx.x >> 5;  // 0..7
    float* S = g_S + (size_t)b * T_ * J_;

    float mx = -3.0e38f, sm = 0.f;
    for (int t = ts; t < T_; t += 8) {
        float v = S[t * J_ + j];
        float nm = fmaxf(mx, v);
        sm = sm * expf(mx - nm) + expf(v - nm);
        mx = nm;
    }
    __shared__ float sM[8][32], sS[8][32];
    sM[ts][lane] = mx;
    sS[ts][lane] = sm;
    __syncthreads();
    if (threadIdx.x < 32) {
        float M = sM[0][lane], SS = sS[0][lane];
#pragma unroll
        for (int r = 1; r < 8; r++) {
            float m2 = sM[r][lane], s2 = sS[r][lane];
            float nm = fmaxf(M, m2);
            SS = SS * expf(M - nm) + s2 * expf(m2 - nm);
            M = nm;
        }
        sM[0][lane] = M;
        sS[0][lane] = SS;
    }
    __syncthreads();
    float M = sM[0][lane];
    float inv = 1.f / sS[0][lane];
    for (int t = ts; t < T_; t += 8) {
        float v = S[t * J_ + j];
        S[t * J_ + j] = expf(v - M) * inv;
    }
}

// ---------------- kernel 6: h[b,d] = sum_t bt * ctx -------------------------
__global__ __launch_bounds__(256) void h_kernel(const float* __restrict__ ctx) {
    const int b = blockIdx.y;
    const int d = blockIdx.x * 256 + threadIdx.x;
    __shared__ float bts[T_];
    for (int i = threadIdx.x; i < T_; i += 256) bts[i] = g_bt[b * T_ + i];
    __syncthreads();
    const float* cp = ctx + (size_t)b * T_ * D_ + d;
    float acc = 0.f;
#pragma unroll 4
    for (int t = 0; t < T_; t++) acc += bts[t] * cp[(size_t)t * D_];
    g_h[b * D_ + d] = acc;
}

// ---------------- kernel 7: GEMM2  U = P @ q  (tf32 mma), fused G assembly --
// Block 128(t) x 128(d), K = 256 (j), K-tile 32.
__global__ __launch_bounds__(256) void gemm2_tc(const float* __restrict__ ctx,
                                                const float* __restrict__ q,
                                                float* __restrict__ out) {
    __shared__ float As[4 * 8 * 128];
    __shared__ float Bs[4 * 16 * 64];

    const int tid = threadIdx.x;
    const int b = blockIdx.z;
    const int m0 = blockIdx.y * 128;
    const int n0 = blockIdx.x * 128;
    const float* Ag = g_S + (size_t)b * T_ * J_;  // P [1024][256]
    const float* Bg = q + (size_t)b * J_ * D_;    // [256][512], n contiguous

    const int lane = tid & 31;
    const int wid = tid >> 5;
    const int warp_m = wid & 1;
    const int warp_n = wid >> 1;

    float acc[4][4][4];
#pragma unroll
    for (int i = 0; i < 4; i++)
#pragma unroll
        for (int j = 0; j < 4; j++)
#pragma unroll
            for (int k = 0; k < 4; k++) acc[i][j][k] = 0.f;

    float4 pa[4], pb[4];
#pragma unroll
    for (int i = 0; i < 4; i++) {
        int f = tid + i * 256;
        int m = f >> 3, k4 = f & 7;            // A indices
        int kb = f >> 5, n4 = f & 31;          // B indices
        pa[i] = *(const float4*)(Ag + (size_t)(m0 + m) * J_ + k4 * 4);
        pb[i] = *(const float4*)(Bg + (size_t)kb * D_ + n0 + n4 * 4);
    }

    const int KT = J_ / 32;
    for (int kt = 0; kt < KT; kt++) {
#pragma unroll
        for (int i = 0; i < 4; i++) {
            int f = tid + i * 256;
            // A scatter
            {
                int m = f >> 3, k4 = f & 7;
                int ka = k4 >> 1;
                int matom = m >> 4, mr = m & 15;
                int ls = (mr & 7) * 4;
                int r = (mr >> 3) + 2 * (k4 & 1);
                float* dst = As + ((ka * 8 + matom) << 7) + r;
#pragma unroll
                for (int j = 0; j < 4; j++) dst[(ls + j) * 4] = tf32r((&pa[i].x)[j]);
            }
            // B scatter: element (k, n4*4+j)
            {
                int kb = f >> 5, n4 = f & 31;
                int ka = kb >> 3, kr = kb & 7;
                int natom = n4 >> 1;
                int nr0 = (n4 & 1) * 4;
                int r = (kr >> 2);
                float* dst = Bs + ((ka * 16 + natom) << 6) + (kr & 3) * 2 + r;
#pragma unroll
                for (int j = 0; j < 4; j++) dst[(nr0 + j) * 8] = tf32r((&pb[i].x)[j]);
            }
        }
        __syncthreads();
        if (kt + 1 < KT) {
#pragma unroll
            for (int i = 0; i < 4; i++) {
                int f = tid + i * 256;
                int m = f >> 3, k4 = f & 7;
                int kb = f >> 5, n4 = f & 31;
                pa[i] = *(const float4*)(Ag + (size_t)(m0 + m) * J_ + (kt + 1) * 32 + k4 * 4);
                pb[i] = *(const float4*)(Bg + (size_t)((kt + 1) * 32 + kb) * D_ + n0 + n4 * 4);
            }
        }
#pragma unroll
        for (int ka = 0; ka < 4; ka++) {
            float4 af[4];
            float2 bf[4];
#pragma unroll
            for (int ma = 0; ma < 4; ma++)
                af[ma] = *(const float4*)&As[((ka * 8 + warp_m * 4 + ma) << 7) + lane * 4];
#pragma unroll
            for (int na = 0; na < 4; na++)
                bf[na] = *(const float2*)&Bs[((ka * 16 + warp_n * 4 + na) << 6) + lane * 2];
#pragma unroll
            for (int ma = 0; ma < 4; ma++)
#pragma unroll
                for (int na = 0; na < 4; na++) MMA_TF32(acc[ma][na], af[ma], bf[na]);
        }
        __syncthreads();
    }

    // epilogue: G = [ctx | U | ctx*U | ctx*h]
    const int g = lane >> 2;
    const int tg = lane & 3;
#pragma unroll
    for (int ma = 0; ma < 4; ma++) {
        int r0 = m0 + warp_m * 64 + ma * 16 + g;
#pragma unroll
        for (int rr = 0; rr < 2; rr++) {
            int m = r0 + rr * 8;
            const float* crow = ctx + ((size_t)(b * T_ + m)) * D_;
            float* orow = out + ((size_t)(b * T_ + m)) * (4 * D_);
#pragma unroll
            for (int na = 0; na < 4; na++) {
                int n = n0 + warp_n * 32 + na * 8 + tg * 2;
                float2 cv = *(const float2*)(crow + n);
                float2 hv = *(const float2*)(g_h + b * D_ + n);
                float u0 = acc[ma][na][rr * 2 + 0];
                float u1 = acc[ma][na][rr * 2 + 1];
                *(float2*)(orow + n) = cv;
                *(float2*)(orow + D_ + n) = make_float2(u0, u1);
                *(float2*)(orow + 2 * D_ + n) = make_float2(cv.x * u0, cv.y * u1);
                *(float2*)(orow + 3 * D_ + n) = make_float2(cv.x * hv.x, cv.y * hv.y);
            }
        }
    }
}

// ---------------- launch -----------------------------------------------------
extern "C" void kernel_launch(void* const* d_in, const int* in_sizes, int n_in,
                              void* d_out, int out_size) {
    const float* ctx = (const float*)d_in[0];
    const float* q = (const float*)d_in[1];
    const float* w = (const float*)d_in[2];
    float* out = (float*)d_out;

    dotw_kernel<<<5120, 256>>>(ctx, q, w);
    gemm1_tc<<<dim3(2, 8, 32), 256>>>(ctx, q, w);
    rowmax_kernel<<<4096, 256>>>();
    bt_kernel<<<32, 256>>>();
    colsoftmax_kernel<<<dim3(8, 32), 256>>>();
    h_kernel<<<dim3(2, 32), 256>>>(ctx);
    gemm2_tc<<<dim3(4, 8, 32), 256>>>(ctx, q, out);
}